// round 1
// baseline (speedup 1.0000x reference)
#include <cuda_runtime.h>
#include <math.h>

// ---------------- problem constants ----------------
#define HH 64
#define PP 64
#define NN 128
#define GG 8
#define KK 4
#define DM 4096
#define II 4096           // H*P
#define GN 1024           // G*N
#define CONVD 6144        // I + 2*GN
#define PROJ 10304        // I + CONVD + H
#define LSEQ 2048
#define BB 2
#define BT 4096           // B*L
#define GRPSZ 512         // I/G

#define OUT_ELEMS (4096*4096)
#define CS_ELEMS  (BB*CONVD*(KK-1))

// ---------------- scratch (device globals; no allocs allowed) ----------------
static __device__ float g_proj[(size_t)BT * PROJ];
static __device__ float g_xbc[(size_t)BT * CONVD];
static __device__ float g_dtp[BT * HH];
static __device__ float g_dA[BT * HH];
static __device__ float g_y[(size_t)BT * II];
static __device__ float g_yn[(size_t)BT * II];

__device__ __forceinline__ float silu_f(float x) {
    return x / (1.0f + __expf(-x));
}
__device__ __forceinline__ float softplus_f(float x) {
    return (x > 20.0f) ? x : log1pf(expf(x));
}

// ---------------- fp32 SIMT GEMM: C[M,N] = A[M,K] * B[N,K]^T ----------------
// 128x128 tile, BK=16, 256 threads, 8x8 per thread, register prefetch.
__device__ __forceinline__ void gemm_body(const float* __restrict__ A,
                                          const float* __restrict__ B,
                                          float* __restrict__ C,
                                          int M, int N, int K) {
    __shared__ __align__(16) float As[16][132];
    __shared__ __align__(16) float Bs[16][132];

    const int tid = threadIdx.x;
    const int tx = tid & 15;
    const int ty = tid >> 4;
    const int row0 = blockIdx.y * 128;
    const int col0 = blockIdx.x * 128;

    const int lr = tid >> 1;          // 0..127
    const int lc = (tid & 1) * 8;     // 0 or 8

    const bool avalid = (row0 + lr) < M;
    const bool bvalid = (col0 + lr) < N;
    const float* Aptr = A + (size_t)(row0 + lr) * K + lc;
    const float* Bptr = B + (size_t)(col0 + lr) * K + lc;

    float4 pa0, pa1, pb0, pb1;
    auto fetch = [&](int kt) {
        if (avalid) {
            pa0 = *(const float4*)(Aptr + kt);
            pa1 = *(const float4*)(Aptr + kt + 4);
        } else {
            pa0 = make_float4(0.f,0.f,0.f,0.f); pa1 = pa0;
        }
        if (bvalid) {
            pb0 = *(const float4*)(Bptr + kt);
            pb1 = *(const float4*)(Bptr + kt + 4);
        } else {
            pb0 = make_float4(0.f,0.f,0.f,0.f); pb1 = pb0;
        }
    };

    float acc[8][8];
#pragma unroll
    for (int i = 0; i < 8; i++)
#pragma unroll
        for (int j = 0; j < 8; j++) acc[i][j] = 0.f;

    fetch(0);
    for (int kt = 0; kt < K; kt += 16) {
        __syncthreads();
        As[lc+0][lr] = pa0.x; As[lc+1][lr] = pa0.y; As[lc+2][lr] = pa0.z; As[lc+3][lr] = pa0.w;
        As[lc+4][lr] = pa1.x; As[lc+5][lr] = pa1.y; As[lc+6][lr] = pa1.z; As[lc+7][lr] = pa1.w;
        Bs[lc+0][lr] = pb0.x; Bs[lc+1][lr] = pb0.y; Bs[lc+2][lr] = pb0.z; Bs[lc+3][lr] = pb0.w;
        Bs[lc+4][lr] = pb1.x; Bs[lc+5][lr] = pb1.y; Bs[lc+6][lr] = pb1.z; Bs[lc+7][lr] = pb1.w;
        __syncthreads();
        if (kt + 16 < K) fetch(kt + 16);

#pragma unroll
        for (int k = 0; k < 16; k++) {
            float4 a0 = *(const float4*)&As[k][ty * 8];
            float4 a1 = *(const float4*)&As[k][ty * 8 + 4];
            float4 b0 = *(const float4*)&Bs[k][tx * 8];
            float4 b1 = *(const float4*)&Bs[k][tx * 8 + 4];
            float ra[8] = {a0.x, a0.y, a0.z, a0.w, a1.x, a1.y, a1.z, a1.w};
            float rb[8] = {b0.x, b0.y, b0.z, b0.w, b1.x, b1.y, b1.z, b1.w};
#pragma unroll
            for (int i = 0; i < 8; i++)
#pragma unroll
                for (int j = 0; j < 8; j++)
                    acc[i][j] = fmaf(ra[i], rb[j], acc[i][j]);
        }
    }

#pragma unroll
    for (int i = 0; i < 8; i++) {
        int m = row0 + ty * 8 + i;
        if (m < M) {
#pragma unroll
            for (int j = 0; j < 8; j++) {
                int n = col0 + tx * 8 + j;
                if (n < N) C[(size_t)m * N + n] = acc[i][j];
            }
        }
    }
}

__global__ __launch_bounds__(256, 2)
void gemm_inproj_kernel(const float* __restrict__ hs, const float* __restrict__ w) {
    gemm_body(hs, w, g_proj, BT, PROJ, DM);
}

__global__ __launch_bounds__(256, 2)
void gemm_outproj_kernel(const float* __restrict__ w, float* __restrict__ out) {
    gemm_body(g_yn, w, out, BT, DM, II);
}

// ---------------- conv1d (depthwise, K=4, causal) + silu; also conv_state ----------------
__global__ void conv_kernel(const float* __restrict__ cw,
                            const float* __restrict__ cb,
                            float* __restrict__ conv_state) {
    int idx = blockIdx.x * blockDim.x + threadIdx.x;  // over BT*CONVD
    if (idx >= BT * CONVD) return;
    int bt = idx / CONVD;
    int c  = idx - bt * CONVD;
    int b = bt >> 11;          // /2048
    int l = bt & 2047;

    const float w0 = cw[c * 4 + 0], w1 = cw[c * 4 + 1], w2 = cw[c * 4 + 2], w3 = cw[c * 4 + 3];
    const size_t colbase = (size_t)II + c;

    float x0 = (l >= 3) ? g_proj[(size_t)(bt - 3) * PROJ + colbase] : 0.f;
    float x1 = (l >= 2) ? g_proj[(size_t)(bt - 2) * PROJ + colbase] : 0.f;
    float x2 = (l >= 1) ? g_proj[(size_t)(bt - 1) * PROJ + colbase] : 0.f;
    float x3 = g_proj[(size_t)bt * PROJ + colbase];

    float v = cb[c] + x0 * w0 + x1 * w1 + x2 * w2 + x3 * w3;
    g_xbc[(size_t)bt * CONVD + c] = silu_f(v);

    if (l >= LSEQ - (KK - 1)) {
        int j = l - (LSEQ - (KK - 1));
        conv_state[(b * CONVD + c) * (KK - 1) + j] = x3;  // raw pre-conv hbc
    }
}

// ---------------- dt_p = softplus(dt + dt_bias); dA = exp(dt_p * -exp(A_log)) ----------------
__global__ void dt_kernel(const float* __restrict__ dt_bias,
                          const float* __restrict__ A_log) {
    int idx = blockIdx.x * blockDim.x + threadIdx.x;  // over BT*H
    if (idx >= BT * HH) return;
    int bt = idx >> 6;
    int h  = idx & 63;
    float dtv = g_proj[(size_t)bt * PROJ + (II + CONVD) + h] + dt_bias[h];
    float dtp = softplus_f(dtv);
    float A = -expf(A_log[h]);
    g_dtp[idx] = dtp;
    g_dA[idx] = expf(dtp * A);
}

// ---------------- sequential SSM scan: 1 CTA per (b,h) ----------------
// 512 threads: thread = p*8 + c, state chunk = 16 n-values.
__global__ __launch_bounds__(512, 1)
void scan_kernel(const float* __restrict__ Dv, float* __restrict__ final_state) {
    const int bh = blockIdx.x;           // 0..127
    const int b = bh >> 6, h = bh & 63;
    const int g = h >> 3;                // group = h / (H/G) = h/8
    const int tid = threadIdx.x;
    const int p = tid >> 3;              // 0..63
    const int c = tid & 7;               // 0..7
    const int n0 = c * 16;

    __shared__ float xs[PP];
    __shared__ float Bsm[NN];
    __shared__ float Csm[NN];
    __shared__ float sc[2];

    float st[16];
#pragma unroll
    for (int i = 0; i < 16; i++) st[i] = 0.f;

    const float Dh = Dv[h];
    const size_t xcol = (size_t)h * PP;
    const size_t bcol = (size_t)II + (size_t)g * NN;
    const size_t ccol = (size_t)II + GN + (size_t)g * NN;

    float pref = 0.f, pdA = 0.f, pdtp = 0.f;
    auto load_t = [&](int t) {
        size_t row = ((size_t)b * LSEQ + t) * CONVD;
        if (tid < 64)        pref = g_xbc[row + xcol + tid];
        else if (tid < 192)  pref = g_xbc[row + bcol + (tid - 64)];
        else if (tid < 320)  pref = g_xbc[row + ccol + (tid - 192)];
        else if (tid == 320) {
            int i2 = (b * LSEQ + t) * HH + h;
            pdA = g_dA[i2];
            pdtp = g_dtp[i2];
        }
    };

    load_t(0);
    for (int t = 0; t < LSEQ; t++) {
        __syncthreads();
        if (tid < 64)        xs[tid] = pref;
        else if (tid < 192)  Bsm[tid - 64] = pref;
        else if (tid < 320)  Csm[tid - 192] = pref;
        else if (tid == 320) { sc[0] = pdA; sc[1] = pdtp; }
        __syncthreads();
        if (t + 1 < LSEQ) load_t(t + 1);

        float dAv = sc[0];
        float xp  = xs[p];
        float dtx = sc[1] * xp;
        float yp = 0.f;
#pragma unroll
        for (int i = 0; i < 16; i++) {
            float bn = Bsm[n0 + i];
            float cn = Csm[n0 + i];
            st[i] = fmaf(st[i], dAv, dtx * bn);
            yp = fmaf(st[i], cn, yp);
        }
        yp += __shfl_xor_sync(0xffffffffu, yp, 1);
        yp += __shfl_xor_sync(0xffffffffu, yp, 2);
        yp += __shfl_xor_sync(0xffffffffu, yp, 4);
        if (c == 0)
            g_y[((size_t)b * LSEQ + t) * II + (size_t)h * PP + p] = yp + Dh * xp;
    }

#pragma unroll
    for (int i = 0; i < 16; i++)
        final_state[((size_t)bh * PP + p) * NN + n0 + i] = st[i];
}

// ---------------- grouped RMS norm * norm_weight * silu(gate) ----------------
__global__ __launch_bounds__(512)
void norm_kernel(const float* __restrict__ nw) {
    const int row = blockIdx.x;          // 0..4095
    const int tid = threadIdx.x;         // 512
    const float* yr = g_y + (size_t)row * II;

    float v[8];
    float ss = 0.f;
#pragma unroll
    for (int i = 0; i < 8; i++) {
        v[i] = yr[tid * 8 + i];
        ss = fmaf(v[i], v[i], ss);
    }
#pragma unroll
    for (int o = 16; o; o >>= 1) ss += __shfl_xor_sync(0xffffffffu, ss, o);

    __shared__ float wsum[16];
    if ((tid & 31) == 0) wsum[tid >> 5] = ss;
    __syncthreads();
    int gid = tid >> 6;                  // group = (tid*8)/512
    float tot = wsum[gid * 2] + wsum[gid * 2 + 1];
    float rs = rsqrtf(tot * (1.0f / GRPSZ) + 1e-5f);

    const float* gr = g_proj + (size_t)row * PROJ;  // gate = first I cols
    float* yo = g_yn + (size_t)row * II;
#pragma unroll
    for (int i = 0; i < 8; i++) {
        int col = tid * 8 + i;
        float gv = gr[col];
        yo[col] = v[i] * rs * nw[col] * silu_f(gv);
    }
}

// ---------------- launch ----------------
extern "C" void kernel_launch(void* const* d_in, const int* in_sizes, int n_in,
                              void* d_out, int out_size) {
    const float* hs        = (const float*)d_in[0];  // (2,2048,4096)
    const float* in_proj_w = (const float*)d_in[1];  // (10304,4096)
    const float* conv_w    = (const float*)d_in[2];  // (6144,4)
    const float* conv_b    = (const float*)d_in[3];  // (6144,)
    const float* dt_bias   = (const float*)d_in[4];  // (64,)
    const float* A_log     = (const float*)d_in[5];  // (64,)
    const float* Dv        = (const float*)d_in[6];  // (64,)
    const float* norm_w    = (const float*)d_in[7];  // (4096,)
    const float* out_w     = (const float*)d_in[8];  // (4096,4096)

    float* out         = (float*)d_out;                  // 16777216
    float* conv_state  = out + OUT_ELEMS;                // 36864
    float* final_state = conv_state + CS_ELEMS;          // 2097152

    // 1. in_proj GEMM: (4096 x 4096) * (10304 x 4096)^T
    {
        dim3 grid((PROJ + 127) / 128, BT / 128);
        gemm_inproj_kernel<<<grid, 256>>>(hs, in_proj_w);
    }
    // 2. conv + silu (+ conv_state)
    {
        int total = BT * CONVD;
        conv_kernel<<<(total + 255) / 256, 256>>>(conv_w, conv_b, conv_state);
    }
    // 3. dt_p / dA
    {
        int total = BT * HH;
        dt_kernel<<<(total + 255) / 256, 256>>>(dt_bias, A_log);
    }
    // 4. sequential scan (+ final_state)
    scan_kernel<<<BB * HH, 512>>>(Dv, final_state);
    // 5. grouped RMS norm * gate
    norm_kernel<<<BT, 512>>>(norm_w);
    // 6. out_proj GEMM: (4096 x 4096) * (4096 x 4096)^T -> d_out
    {
        dim3 grid(DM / 128, BT / 128);
        gemm_outproj_kernel<<<grid, 256>>>(out_w, out);
    }
}

// round 2
// speedup vs baseline: 2.1507x; 2.1507x over previous
#include <cuda_runtime.h>
#include <math.h>
#include <stdint.h>

// ---------------- problem constants ----------------
#define HH 64
#define PP 64
#define NN 128
#define GG 8
#define KK 4
#define DM 4096
#define II 4096           // H*P
#define GN 1024           // G*N
#define CONVD 6144        // I + 2*GN
#define PROJ 10304        // I + CONVD + H
#define LSEQ 2048
#define BB 2
#define BT 4096           // B*L
#define GRPSZ 512         // I/G

#define OUT_ELEMS (4096*4096)
#define CS_ELEMS  (BB*CONVD*(KK-1))

// ---------------- scratch (device globals; no allocs allowed) ----------------
static __device__ float g_proj[(size_t)BT * PROJ];
static __device__ float g_xbc[(size_t)BT * CONVD];
static __device__ float g_dtp[BT * HH];
static __device__ float g_dA[BT * HH];
static __device__ float g_y[(size_t)BT * II];
static __device__ float g_yn[(size_t)BT * II];
static __device__ float g_a32[(size_t)BT * DM];        // tf32-rounded hidden_states
static __device__ float g_w32[(size_t)PROJ * DM];      // tf32-rounded weights (reused)

__device__ __forceinline__ float silu_f(float x) {
    return x / (1.0f + __expf(-x));
}
__device__ __forceinline__ float softplus_f(float x) {
    return (x > 20.0f) ? x : log1pf(expf(x));
}
__device__ __forceinline__ float tf32_rna(float x) {
    uint32_t r;
    asm("cvt.rna.tf32.f32 %0, %1;" : "=r"(r) : "f"(x));
    return __uint_as_float(r);
}

// ---------------- tf32 rounding pass (RNA, zero-mean error) ----------------
__global__ void round_tf32_kernel(const float* __restrict__ src,
                                  float* __restrict__ dst, int n4) {
    int i = blockIdx.x * blockDim.x + threadIdx.x;
    if (i >= n4) return;
    float4 v = ((const float4*)src)[i];
    v.x = tf32_rna(v.x); v.y = tf32_rna(v.y);
    v.z = tf32_rna(v.z); v.w = tf32_rna(v.w);
    ((float4*)dst)[i] = v;
}

// ---------------- tensor-core tf32 GEMM: C[M,N] = A[M,K] * B[N,K]^T ----------------
// CTA 128x128, BK=16, 256 thr / 8 warps (2x4 of 64x32 warp tiles),
// cp.async double-buffered, smem row stride 20 floats (conflict-free frag loads).
__global__ __launch_bounds__(256, 2)
void gemm_tc_kernel(const float* __restrict__ A, const float* __restrict__ B,
                    float* __restrict__ C, int M, int N, int K) {
    __shared__ __align__(16) float As[2][128][20];
    __shared__ __align__(16) float Bs[2][128][20];

    const int tid  = threadIdx.x;
    const int warp = tid >> 5, lane = tid & 31;
    const int g    = lane >> 2, tig = lane & 3;
    const int wm   = (warp >> 2) * 64;    // warp m offset (0 or 64)
    const int wn   = (warp & 3) * 32;     // warp n offset
    const int row0 = blockIdx.y * 128;
    const int col0 = blockIdx.x * 128;

    // cp.async assignment: 2 threads per row, 8 floats (2x16B) each
    const int lr = tid >> 1;
    const int lk = (tid & 1) * 8;
    const float* Ag = A + (size_t)(row0 + lr) * K + lk;
    const float* Bg = B + (size_t)(col0 + lr) * K + lk;
    const int bsz = ((col0 + lr) < N) ? 16 : 0;   // zero-fill OOB B rows

    float acc[4][4][4];
#pragma unroll
    for (int mt = 0; mt < 4; mt++)
#pragma unroll
        for (int nt = 0; nt < 4; nt++)
#pragma unroll
            for (int i = 0; i < 4; i++) acc[mt][nt][i] = 0.f;

    auto load_tiles = [&](int buf, int kt) {
        uint32_t a_s = (uint32_t)__cvta_generic_to_shared(&As[buf][lr][lk]);
        uint32_t b_s = (uint32_t)__cvta_generic_to_shared(&Bs[buf][lr][lk]);
        const float* ap = Ag + kt;
        const float* bp = Bg + kt;
        asm volatile("cp.async.cg.shared.global [%0], [%1], 16;\n" :: "r"(a_s), "l"(ap));
        asm volatile("cp.async.cg.shared.global [%0], [%1], 16;\n" :: "r"(a_s + 16), "l"(ap + 4));
        asm volatile("cp.async.cg.shared.global [%0], [%1], 16, %2;\n" :: "r"(b_s), "l"(bp), "r"(bsz));
        asm volatile("cp.async.cg.shared.global [%0], [%1], 16, %2;\n" :: "r"(b_s + 16), "l"(bp + 4), "r"(bsz));
    };

    const int nk = K / 16;
    load_tiles(0, 0);
    asm volatile("cp.async.commit_group;\n");

    for (int it = 0; it < nk; it++) {
        asm volatile("cp.async.wait_group 0;\n");
        __syncthreads();
        if (it + 1 < nk) {
            load_tiles((it + 1) & 1, (it + 1) * 16);
            asm volatile("cp.async.commit_group;\n");
        }
        const int buf = it & 1;
#pragma unroll
        for (int ks = 0; ks < 2; ks++) {
            const int k0 = ks * 8;
            uint32_t af[4][4], bf[4][2];
#pragma unroll
            for (int mt = 0; mt < 4; mt++) {
                int r = wm + mt * 16 + g;
                af[mt][0] = __float_as_uint(As[buf][r][k0 + tig]);
                af[mt][1] = __float_as_uint(As[buf][r + 8][k0 + tig]);
                af[mt][2] = __float_as_uint(As[buf][r][k0 + 4 + tig]);
                af[mt][3] = __float_as_uint(As[buf][r + 8][k0 + 4 + tig]);
            }
#pragma unroll
            for (int nt = 0; nt < 4; nt++) {
                int cc = wn + nt * 8 + g;
                bf[nt][0] = __float_as_uint(Bs[buf][cc][k0 + tig]);
                bf[nt][1] = __float_as_uint(Bs[buf][cc][k0 + 4 + tig]);
            }
#pragma unroll
            for (int mt = 0; mt < 4; mt++)
#pragma unroll
                for (int nt = 0; nt < 4; nt++)
                    asm volatile(
                        "mma.sync.aligned.m16n8k8.row.col.f32.tf32.tf32.f32 "
                        "{%0,%1,%2,%3}, {%4,%5,%6,%7}, {%8,%9}, {%0,%1,%2,%3};\n"
                        : "+f"(acc[mt][nt][0]), "+f"(acc[mt][nt][1]),
                          "+f"(acc[mt][nt][2]), "+f"(acc[mt][nt][3])
                        : "r"(af[mt][0]), "r"(af[mt][1]), "r"(af[mt][2]), "r"(af[mt][3]),
                          "r"(bf[nt][0]), "r"(bf[nt][1]));
        }
    }

#pragma unroll
    for (int mt = 0; mt < 4; mt++) {
        int r = row0 + wm + mt * 16 + g;
#pragma unroll
        for (int nt = 0; nt < 4; nt++) {
            int cc = col0 + wn + nt * 8 + 2 * tig;
            if (cc < N) {   // N even, cc even -> cc+1 also valid
                float* p0 = C + (size_t)r * N + cc;
                float* p1 = C + (size_t)(r + 8) * N + cc;
                p0[0] = acc[mt][nt][0]; p0[1] = acc[mt][nt][1];
                p1[0] = acc[mt][nt][2]; p1[1] = acc[mt][nt][3];
            }
        }
    }
}

// ---------------- conv1d (depthwise, K=4, causal) + silu; also conv_state ----------------
__global__ void conv_kernel(const float* __restrict__ cw,
                            const float* __restrict__ cb,
                            float* __restrict__ conv_state) {
    int idx = blockIdx.x * blockDim.x + threadIdx.x;  // over BT*CONVD
    if (idx >= BT * CONVD) return;
    int bt = idx / CONVD;
    int c  = idx - bt * CONVD;
    int b = bt >> 11;
    int l = bt & 2047;

    const float w0 = cw[c * 4 + 0], w1 = cw[c * 4 + 1], w2 = cw[c * 4 + 2], w3 = cw[c * 4 + 3];
    const size_t colbase = (size_t)II + c;

    float x0 = (l >= 3) ? g_proj[(size_t)(bt - 3) * PROJ + colbase] : 0.f;
    float x1 = (l >= 2) ? g_proj[(size_t)(bt - 2) * PROJ + colbase] : 0.f;
    float x2 = (l >= 1) ? g_proj[(size_t)(bt - 1) * PROJ + colbase] : 0.f;
    float x3 = g_proj[(size_t)bt * PROJ + colbase];

    float v = cb[c] + x0 * w0 + x1 * w1 + x2 * w2 + x3 * w3;
    g_xbc[(size_t)bt * CONVD + c] = silu_f(v);

    if (l >= LSEQ - (KK - 1)) {
        int j = l - (LSEQ - (KK - 1));
        conv_state[(b * CONVD + c) * (KK - 1) + j] = x3;
    }
}

// ---------------- dt_p = softplus(dt + dt_bias); dA = exp(dt_p * -exp(A_log)) ----------------
__global__ void dt_kernel(const float* __restrict__ dt_bias,
                          const float* __restrict__ A_log) {
    int idx = blockIdx.x * blockDim.x + threadIdx.x;  // over BT*H
    if (idx >= BT * HH) return;
    int bt = idx >> 6;
    int h  = idx & 63;
    float dtv = g_proj[(size_t)bt * PROJ + (II + CONVD) + h] + dt_bias[h];
    float dtp = softplus_f(dtv);
    float A = -expf(A_log[h]);
    g_dtp[idx] = dtp;
    g_dA[idx] = expf(dtp * A);
}

// ---------------- sequential SSM scan: 1 CTA per (b,h) ----------------
__global__ __launch_bounds__(512, 1)
void scan_kernel(const float* __restrict__ Dv, float* __restrict__ final_state) {
    const int bh = blockIdx.x;
    const int b = bh >> 6, h = bh & 63;
    const int g = h >> 3;
    const int tid = threadIdx.x;
    const int p = tid >> 3;
    const int c = tid & 7;
    const int n0 = c * 16;

    __shared__ float xs[PP];
    __shared__ float Bsm[NN];
    __shared__ float Csm[NN];
    __shared__ float sc[2];

    float st[16];
#pragma unroll
    for (int i = 0; i < 16; i++) st[i] = 0.f;

    const float Dh = Dv[h];
    const size_t xcol = (size_t)h * PP;
    const size_t bcol = (size_t)II + (size_t)g * NN;
    const size_t ccol = (size_t)II + GN + (size_t)g * NN;

    float pref = 0.f, pdA = 0.f, pdtp = 0.f;
    auto load_t = [&](int t) {
        size_t row = ((size_t)b * LSEQ + t) * CONVD;
        if (tid < 64)        pref = g_xbc[row + xcol + tid];
        else if (tid < 192)  pref = g_xbc[row + bcol + (tid - 64)];
        else if (tid < 320)  pref = g_xbc[row + ccol + (tid - 192)];
        else if (tid == 320) {
            int i2 = (b * LSEQ + t) * HH + h;
            pdA = g_dA[i2];
            pdtp = g_dtp[i2];
        }
    };

    load_t(0);
    for (int t = 0; t < LSEQ; t++) {
        __syncthreads();
        if (tid < 64)        xs[tid] = pref;
        else if (tid < 192)  Bsm[tid - 64] = pref;
        else if (tid < 320)  Csm[tid - 192] = pref;
        else if (tid == 320) { sc[0] = pdA; sc[1] = pdtp; }
        __syncthreads();
        if (t + 1 < LSEQ) load_t(t + 1);

        float dAv = sc[0];
        float xp  = xs[p];
        float dtx = sc[1] * xp;
        float yp = 0.f;
#pragma unroll
        for (int i = 0; i < 16; i++) {
            float bn = Bsm[n0 + i];
            float cn = Csm[n0 + i];
            st[i] = fmaf(st[i], dAv, dtx * bn);
            yp = fmaf(st[i], cn, yp);
        }
        yp += __shfl_xor_sync(0xffffffffu, yp, 1);
        yp += __shfl_xor_sync(0xffffffffu, yp, 2);
        yp += __shfl_xor_sync(0xffffffffu, yp, 4);
        if (c == 0)
            g_y[((size_t)b * LSEQ + t) * II + (size_t)h * PP + p] = yp + Dh * xp;
    }

#pragma unroll
    for (int i = 0; i < 16; i++)
        final_state[((size_t)bh * PP + p) * NN + n0 + i] = st[i];
}

// ---------------- grouped RMS norm * norm_weight * silu(gate) ----------------
// Output is tf32-rounded (RNA) so the out_proj GEMM reads exact tf32 operands.
__global__ __launch_bounds__(512)
void norm_kernel(const float* __restrict__ nw) {
    const int row = blockIdx.x;
    const int tid = threadIdx.x;
    const float* yr = g_y + (size_t)row * II;

    float v[8];
    float ss = 0.f;
#pragma unroll
    for (int i = 0; i < 8; i++) {
        v[i] = yr[tid * 8 + i];
        ss = fmaf(v[i], v[i], ss);
    }
#pragma unroll
    for (int o = 16; o; o >>= 1) ss += __shfl_xor_sync(0xffffffffu, ss, o);

    __shared__ float wsum[16];
    if ((tid & 31) == 0) wsum[tid >> 5] = ss;
    __syncthreads();
    int gid = tid >> 6;
    float tot = wsum[gid * 2] + wsum[gid * 2 + 1];
    float rs = rsqrtf(tot * (1.0f / GRPSZ) + 1e-5f);

    const float* gr = g_proj + (size_t)row * PROJ;
    float* yo = g_yn + (size_t)row * II;
#pragma unroll
    for (int i = 0; i < 8; i++) {
        int col = tid * 8 + i;
        float gv = gr[col];
        yo[col] = tf32_rna(v[i] * rs * nw[col] * silu_f(gv));
    }
}

// ---------------- launch ----------------
extern "C" void kernel_launch(void* const* d_in, const int* in_sizes, int n_in,
                              void* d_out, int out_size) {
    const float* hs        = (const float*)d_in[0];
    const float* in_proj_w = (const float*)d_in[1];
    const float* conv_w    = (const float*)d_in[2];
    const float* conv_b    = (const float*)d_in[3];
    const float* dt_bias   = (const float*)d_in[4];
    const float* A_log     = (const float*)d_in[5];
    const float* Dv        = (const float*)d_in[6];
    const float* norm_w    = (const float*)d_in[7];
    const float* out_w     = (const float*)d_in[8];

    float* out         = (float*)d_out;
    float* conv_state  = out + OUT_ELEMS;
    float* final_state = conv_state + CS_ELEMS;

    float* pa32; cudaGetSymbolAddress((void**)&pa32, g_a32);
    float* pw32; cudaGetSymbolAddress((void**)&pw32, g_w32);

    // 0. tf32-round A/B operands for in_proj GEMM
    {
        int n4 = (BT * DM) / 4;
        round_tf32_kernel<<<(n4 + 255) / 256, 256>>>(hs, pa32, n4);
    }
    {
        int n4 = (PROJ * DM) / 4;
        round_tf32_kernel<<<(n4 + 255) / 256, 256>>>(in_proj_w, pw32, n4);
    }
    // 1. in_proj GEMM (tensor cores, tf32)
    {
        float* pproj; cudaGetSymbolAddress((void**)&pproj, g_proj);
        dim3 grid((PROJ + 127) / 128, BT / 128);
        gemm_tc_kernel<<<grid, 256>>>(pa32, pw32, pproj, BT, PROJ, DM);
    }
    // 2. conv + silu (+ conv_state)
    {
        int total = BT * CONVD;
        conv_kernel<<<(total + 255) / 256, 256>>>(conv_w, conv_b, conv_state);
    }
    // 3. dt_p / dA
    {
        int total = BT * HH;
        dt_kernel<<<(total + 255) / 256, 256>>>(dt_bias, A_log);
    }
    // 4. sequential scan (+ final_state)
    scan_kernel<<<BB * HH, 512>>>(Dv, final_state);
    // 5. grouped RMS norm * gate (tf32-rounded output)
    norm_kernel<<<BT, 512>>>(norm_w);
    // 6. round out_proj weight, then out_proj GEMM -> d_out
    {
        int n4 = (DM * II) / 4;
        round_tf32_kernel<<<(n4 + 255) / 256, 256>>>(out_w, pw32, n4);
    }
    {
        float* pyn; cudaGetSymbolAddress((void**)&pyn, g_yn);
        dim3 grid(DM / 128, BT / 128);
        gemm_tc_kernel<<<grid, 256>>>(pyn, pw32, out, BT, DM, II);
    }
}